// round 5
// baseline (speedup 1.0000x reference)
#include <cuda_runtime.h>
#include <math.h>

#define BSZ   512
#define SLEN  63
#define DD    256
#define VDIM  512
#define RR    196
#define NOUTD 3000
#define STK   (SLEN + 2)

// ---------------- scratch (static device arrays; no allocation) -------------
__device__ float g_vv   [(size_t)BSZ * RR * DD];
__device__ float g_wvi  [(size_t)BSZ * RR * DD];
__device__ float g_gl   [(size_t)BSZ * SLEN * 768];
__device__ float g_buffh[(size_t)BSZ * SLEN * DD];
__device__ float g_buffc[(size_t)BSZ * SLEN * DD];
__device__ float g_stackh[(size_t)BSZ * STK * DD];
__device__ float g_stackc[(size_t)BSZ * STK * DD];
__device__ float g_gates[(size_t)BSZ * 1280];
__device__ float g_r    [BSZ * DD];
__device__ float g_wq   [BSZ * DD];
__device__ float g_att  [BSZ * DD];
__device__ float g_hid  [BSZ * DD];
__device__ int   g_ptr  [BSZ];

// ---------------- packed f32x2 helpers --------------------------------------
__device__ __forceinline__ unsigned long long pk2(float lo, float hi) {
    unsigned long long r;
    asm("mov.b64 %0, {%1, %2};" : "=l"(r) : "f"(lo), "f"(hi));
    return r;
}
__device__ __forceinline__ void upk2(unsigned long long v, float& lo, float& hi) {
    asm("mov.b64 {%0, %1}, %2;" : "=f"(lo), "=f"(hi) : "l"(v));
}
__device__ __forceinline__ unsigned long long ff2(unsigned long long a,
                                                  unsigned long long b,
                                                  unsigned long long c) {
    unsigned long long d;
    asm("fma.rn.f32x2 %0, %1, %2, %3;" : "=l"(d) : "l"(a), "l"(b), "l"(c));
    return d;
}
__device__ __forceinline__ float sigm(float x) { return 1.0f / (1.0f + expf(-x)); }

// ---------------------------------------------------------------------------
// C[m, coloff+n] = act( sum_k A[row(m),k] * W[n,k] + bias[n] )
// BM=128, BN=64, BK=16, 256 threads, 8x4 microtile. M%128==0, K%16==0.
// act: 0 none, 1 tanh, 2 sigmoid.
// ---------------------------------------------------------------------------
__global__ __launch_bounds__(256) void gemm_k(
    const float* __restrict__ A, const int* __restrict__ rowidx,
    const float* __restrict__ W, const float* __restrict__ bias,
    float* __restrict__ C, int N, int K, int ldc, int coloff, int act)
{
    __shared__ float As[16][132];
    __shared__ float Ws[16][68];
    const int tid = threadIdx.x;
    const int tx = tid & 15, ty = tid >> 4;
    const int lr = tid >> 2, lc = tid & 3;
    const long bm = (long)blockIdx.x * 128;
    const int  bn = blockIdx.y * 64;

    long ar0 = bm + lr, ar1 = bm + lr + 64;
    if (rowidx) { ar0 = rowidx[ar0]; ar1 = rowidx[ar1]; }
    const float* Ap0 = A + ar0 * (long)K;
    const float* Ap1 = A + ar1 * (long)K;
    const int wr = bn + lr;
    const bool wok = (wr < N);
    const float* Wp = W + (long)wr * K;

    unsigned long long acc[4][4];
#pragma unroll
    for (int p = 0; p < 4; p++)
#pragma unroll
        for (int c = 0; c < 4; c++) acc[p][c] = 0ULL;

    for (int k0 = 0; k0 < K; k0 += 16) {
        float4 a0 = *(const float4*)(Ap0 + k0 + lc * 4);
        float4 a1 = *(const float4*)(Ap1 + k0 + lc * 4);
        float4 w0 = wok ? *(const float4*)(Wp + k0 + lc * 4)
                        : make_float4(0.f, 0.f, 0.f, 0.f);
        __syncthreads();
        As[lc*4+0][lr] = a0.x; As[lc*4+1][lr] = a0.y;
        As[lc*4+2][lr] = a0.z; As[lc*4+3][lr] = a0.w;
        As[lc*4+0][lr+64] = a1.x; As[lc*4+1][lr+64] = a1.y;
        As[lc*4+2][lr+64] = a1.z; As[lc*4+3][lr+64] = a1.w;
        Ws[lc*4+0][lr] = w0.x; Ws[lc*4+1][lr] = w0.y;
        Ws[lc*4+2][lr] = w0.z; Ws[lc*4+3][lr] = w0.w;
        __syncthreads();
#pragma unroll
        for (int k = 0; k < 16; k++) {
            const float4 aA = *(const float4*)&As[k][ty*8];
            const float4 aB = *(const float4*)&As[k][ty*8+4];
            const float4 bb = *(const float4*)&Ws[k][tx*4];
            unsigned long long ap[4] = { pk2(aA.x,aA.y), pk2(aA.z,aA.w),
                                         pk2(aB.x,aB.y), pk2(aB.z,aB.w) };
            unsigned long long bd[4] = { pk2(bb.x,bb.x), pk2(bb.y,bb.y),
                                         pk2(bb.z,bb.z), pk2(bb.w,bb.w) };
#pragma unroll
            for (int p = 0; p < 4; p++)
#pragma unroll
                for (int c = 0; c < 4; c++)
                    acc[p][c] = ff2(ap[p], bd[c], acc[p][c]);
        }
    }

#pragma unroll
    for (int p = 0; p < 4; p++) {
        const long r0 = bm + ty*8 + p*2;
#pragma unroll
        for (int c = 0; c < 4; c++) {
            const int col = bn + tx*4 + c;
            if (col < N) {
                float lo, hi; upk2(acc[p][c], lo, hi);
                const float bv = bias ? bias[col] : 0.0f;
                lo += bv; hi += bv;
                if (act == 1)      { lo = tanhf(lo); hi = tanhf(hi); }
                else if (act == 2) { lo = sigm(lo);  hi = sigm(hi);  }
                C[r0 * (long)ldc + coloff + col] = lo;
                C[(r0+1) * (long)ldc + coloff + col] = hi;
            }
        }
    }
}

// ---------------- leaf combine: c=i*u, h=o*tanh(c) ---------------------------
__global__ void leaf_combine_k()
{
    const long i = (long)blockIdx.x * blockDim.x + threadIdx.x;
    const long row = i >> 8;
    const int  d = (int)(i & 255);
    const float gi = g_gl[row*768 + d];
    const float gu = g_gl[row*768 + 256 + d];
    const float go = g_gl[row*768 + 512 + d];
    const float bc = gi * gu;
    g_buffc[i] = bc;
    g_buffh[i] = go * tanhf(bc);
}

// ---------------- zero stacks + ptr ------------------------------------------
__global__ void scan_init_k()
{
    const long n = (long)BSZ * STK * DD;
    const long i0 = (long)blockIdx.x * blockDim.x + threadIdx.x;
    for (long i = i0; i < n; i += (long)gridDim.x * blockDim.x) {
        g_stackh[i] = 0.0f;
        g_stackc[i] = 0.0f;
    }
    if (i0 < BSZ) g_ptr[(int)i0] = 0;
}

// ---------------------------------------------------------------------------
// Gate pre-activations for step t. Per b:
//  [0:256)=hsum@Ui^T  [256:512)=hsum@Uo^T  [512:768)=hsum@Uu^T
//  [768:1024)=h_left@Uf^T  [1024:1280)=h_right@Uf^T
// BM=64(batch) x BN=64, 256 thr, 4x4 micro; early-exit if tile has no reduce.
// ---------------------------------------------------------------------------
__global__ __launch_bounds__(256) void step_gates_k(
    int t, const int* __restrict__ ops,
    const float* __restrict__ Ui, const float* __restrict__ Uo,
    const float* __restrict__ Uu, const float* __restrict__ Uf)
{
    __shared__ float As[16][68];
    __shared__ float Ws[16][68];
    __shared__ int sh_r[64], sh_l[64];
    __shared__ int anyred;

    const int tid = threadIdx.x;
    const int b0 = blockIdx.x * 64;
    if (tid == 0) anyred = 0;
    __syncthreads();
    if (tid < 64) {
        const int b = b0 + tid;
        const int p = g_ptr[b];
        sh_r[tid] = max(p - 1, 0);
        sh_l[tid] = max(p - 2, 0);
        if (ops[b * SLEN + t] == 1) anyred = 1;
    }
    __syncthreads();
    if (!anyred) return;

    const int seg = blockIdx.y >> 2;             // 0:i 1:o 2:u 3:f1 4:f2
    const int colbase = (blockIdx.y & 3) * 64;
    const float* W = (seg == 0) ? Ui : (seg == 1) ? Uo : (seg == 2) ? Uu : Uf;

    const int tx = tid & 15, ty = tid >> 4;
    const int lr = tid >> 2, lc = tid & 3;

    const float* Wp = W + (long)(colbase + lr) * DD;
    const float* SHb = g_stackh + (long)(b0 + lr) * STK * DD;
    const float* Sr = SHb + sh_r[lr] * DD;       // right child h
    const float* Sl = SHb + sh_l[lr] * DD;       // left child h

    unsigned long long acc[2][4];
#pragma unroll
    for (int p = 0; p < 2; p++)
#pragma unroll
        for (int c = 0; c < 4; c++) acc[p][c] = 0ULL;

    for (int k0 = 0; k0 < DD; k0 += 16) {
        float4 av;
        if (seg < 3) {
            const float4 x = *(const float4*)(Sr + k0 + lc*4);
            const float4 y = *(const float4*)(Sl + k0 + lc*4);
            av = make_float4(x.x+y.x, x.y+y.y, x.z+y.z, x.w+y.w);
        } else if (seg == 3) {
            av = *(const float4*)(Sl + k0 + lc*4);
        } else {
            av = *(const float4*)(Sr + k0 + lc*4);
        }
        const float4 wv = *(const float4*)(Wp + k0 + lc*4);
        __syncthreads();
        As[lc*4+0][lr] = av.x; As[lc*4+1][lr] = av.y;
        As[lc*4+2][lr] = av.z; As[lc*4+3][lr] = av.w;
        Ws[lc*4+0][lr] = wv.x; Ws[lc*4+1][lr] = wv.y;
        Ws[lc*4+2][lr] = wv.z; Ws[lc*4+3][lr] = wv.w;
        __syncthreads();
#pragma unroll
        for (int k = 0; k < 16; k++) {
            const float4 aa = *(const float4*)&As[k][ty*4];
            const float4 bb = *(const float4*)&Ws[k][tx*4];
            unsigned long long ap[2] = { pk2(aa.x,aa.y), pk2(aa.z,aa.w) };
            unsigned long long bd[4] = { pk2(bb.x,bb.x), pk2(bb.y,bb.y),
                                         pk2(bb.z,bb.z), pk2(bb.w,bb.w) };
#pragma unroll
            for (int p = 0; p < 2; p++)
#pragma unroll
                for (int c = 0; c < 4; c++)
                    acc[p][c] = ff2(ap[p], bd[c], acc[p][c]);
        }
    }

#pragma unroll
    for (int p = 0; p < 2; p++) {
        const long row = b0 + ty*4 + p*2;
#pragma unroll
        for (int c = 0; c < 4; c++) {
            const int col = seg * 256 + colbase + tx*4 + c;
            float lo, hi; upk2(acc[p][c], lo, hi);
            g_gates[row * 1280 + col] = lo;
            g_gates[(row+1) * 1280 + col] = hi;
        }
    }
}

// ---------------- cell update, stack write, ptr update -----------------------
__global__ void step_update_k(
    int t, const int* __restrict__ ops,
    const float* __restrict__ Uib, const float* __restrict__ Uob,
    const float* __restrict__ Uub, const float* __restrict__ Ufb)
{
    const int b = blockIdx.x;
    const int d = threadIdx.x;
    const int op = ops[b * SLEN + t];
    const int p = g_ptr[b];
    const int rix = max(p - 1, 0);
    const int lix = max(p - 2, 0);
    const long base = (long)b * STK * DD;

    if (op == 1) {
        const float* G = g_gates + (long)b * 1280;
        const float ig = sigm(G[d] + Uib[d]);
        const float og = sigm(G[256 + d] + Uob[d]);
        const float ug = tanhf(G[512 + d] + Uub[d]);
        const float f1 = sigm(G[768 + d] + Ufb[d]);
        const float f2 = sigm(G[1024 + d] + Ufb[d]);
        const float c1 = g_stackc[base + (long)lix * DD + d];
        const float c2 = g_stackc[base + (long)rix * DD + d];
        const float cn = ig * ug + f1 * c1 + f2 * c2;
        g_stackc[base + (long)lix * DD + d] = cn;
        g_stackh[base + (long)lix * DD + d] = og * tanhf(cn);
    } else if (op == 0) {
        const long bi = ((long)b * SLEN + t) * DD + d;
        g_stackh[base + (long)p * DD + d] = g_buffh[bi];
        g_stackc[base + (long)p * DD + d] = g_buffc[bi];
    }
    __syncthreads();
    if (d == 0)
        g_ptr[b] = p + (op == 0 ? 1 : (op == 1 ? -1 : 0));
}

// ---------------- root gather ------------------------------------------------
__global__ void r_gather_k()
{
    const int b = blockIdx.x, d = threadIdx.x;
    const int ix = max(g_ptr[b] - 1, 0);
    g_r[b * DD + d] = g_stackh[((long)b * STK + ix) * DD + d];
}

// ---------------- fused attention: scores -> softmax -> weighted sum ---------
__global__ void attention_k(const float* __restrict__ WPw,
                            const float* __restrict__ WPb)
{
    const int b = blockIdx.x, tid = threadIdx.x;
    const int warp = tid >> 5, lane = tid & 31;
    __shared__ float s_wq[256], s_wp[256], s_sc[RR], red[16];

    s_wq[tid] = g_wq[b * DD + tid];
    s_wp[tid] = WPw[tid];
    __syncthreads();

    const float wpb = WPb[0];
    for (int r = warp; r < RR; r += 8) {
        const float* vrow = g_wvi + ((long)b * RR + r) * DD;
        float acc = 0.f;
        for (int d = lane; d < DD; d += 32)
            acc += tanhf(s_wq[d] + vrow[d]) * s_wp[d];
#pragma unroll
        for (int o = 16; o; o >>= 1) acc += __shfl_xor_sync(~0u, acc, o);
        if (lane == 0) s_sc[r] = acc + wpb;
    }
    __syncthreads();

    float v = (tid < RR) ? s_sc[tid] : -1e30f;
    float m = v;
#pragma unroll
    for (int o = 16; o; o >>= 1) m = fmaxf(m, __shfl_xor_sync(~0u, m, o));
    if (lane == 0) red[warp] = m;
    __syncthreads();
    if (tid == 0) {
        float mm = red[0];
        for (int i = 1; i < 8; i++) mm = fmaxf(mm, red[i]);
        red[0] = mm;
    }
    __syncthreads();
    const float mm = red[0];
    float e = (tid < RR) ? expf(v - mm) : 0.f;
    float s = e;
#pragma unroll
    for (int o = 16; o; o >>= 1) s += __shfl_xor_sync(~0u, s, o);
    if (lane == 0) red[8 + warp] = s;
    __syncthreads();
    if (tid == 0) {
        float ss = 0.f;
        for (int i = 0; i < 8; i++) ss += red[8 + i];
        red[8] = ss;
    }
    __syncthreads();
    const float inv = 1.0f / red[8];
    if (tid < RR) s_sc[tid] = e * inv;
    __syncthreads();

    float acc = g_r[b * DD + tid];
    const float* vb = g_vv + (long)b * RR * DD;
    for (int r = 0; r < RR; r++)
        acc += s_sc[r] * vb[r * DD + tid];
    g_att[b * DD + tid] = acc;
}

// ---------------------------------------------------------------------------
template <typename T>
static float* symaddr(T& sym) {
    void* p = nullptr;
    cudaGetSymbolAddress(&p, sym);
    return (float*)p;
}

extern "C" void kernel_launch(void* const* d_in, const int* in_sizes, int n_in,
                              void* d_out, int out_size)
{
    const float* v         = (const float*)d_in[0];
    const int*   questions = (const int*)d_in[1];
    const int*   ops       = (const int*)d_in[2];
    int i = (n_in >= 30) ? 4 : 3;   // skip scalar 'bs' if present
    const float* wembed = (const float*)d_in[i++];
    const float* W_w  = (const float*)d_in[i++]; const float* W_b  = (const float*)d_in[i++];
    const float* Wi_w = (const float*)d_in[i++]; const float* Wi_b = (const float*)d_in[i++];
    const float* Wu_w = (const float*)d_in[i++]; const float* Wu_b = (const float*)d_in[i++];
    const float* Wo_w = (const float*)d_in[i++]; const float* Wo_b = (const float*)d_in[i++];
    const float* Ui_w = (const float*)d_in[i++]; const float* Ui_b = (const float*)d_in[i++];
    const float* Uf_w = (const float*)d_in[i++]; const float* Uf_b = (const float*)d_in[i++];
    const float* Uo_w = (const float*)d_in[i++]; const float* Uo_b = (const float*)d_in[i++];
    const float* Uu_w = (const float*)d_in[i++]; const float* Uu_b = (const float*)d_in[i++];
    const float* WQ_w = (const float*)d_in[i++]; const float* WQ_b = (const float*)d_in[i++];
    const float* WV_w = (const float*)d_in[i++];
    const float* WP_w = (const float*)d_in[i++]; const float* WP_b = (const float*)d_in[i++];
    const float* FC1_w = (const float*)d_in[i++]; const float* FC1_b = (const float*)d_in[i++];
    const float* FC2_w = (const float*)d_in[i++]; const float* FC2_b = (const float*)d_in[i++];
    float* out = (float*)d_out;

    float* p_vv   = symaddr(g_vv);
    float* p_wvi  = symaddr(g_wvi);
    float* p_gl   = symaddr(g_gl);
    float* p_r    = symaddr(g_r);
    float* p_wq   = symaddr(g_wq);
    float* p_att  = symaddr(g_att);
    float* p_hid  = symaddr(g_hid);

    // reset scan state (graph replays must be deterministic)
    scan_init_k<<<2048, 256>>>();

    // vv = tanh(v @ W_w^T + W_b)   [100352, 256], K=512
    gemm_k<<<dim3(784, 4), 256>>>(v, nullptr, W_w, W_b, p_vv, DD, VDIM, DD, 0, 1);
    // wvi = vv @ WV_w^T            [100352, 256], K=256
    gemm_k<<<dim3(784, 4), 256>>>(p_vv, nullptr, WV_w, nullptr, p_wvi, DD, DD, DD, 0, 0);

    // leaf gates from gathered embeddings   [32256, 256] each
    gemm_k<<<dim3(252, 4), 256>>>(wembed, questions, Wi_w, Wi_b, p_gl, DD, DD, 768, 0,   2);
    gemm_k<<<dim3(252, 4), 256>>>(wembed, questions, Wu_w, Wu_b, p_gl, DD, DD, 768, 256, 1);
    gemm_k<<<dim3(252, 4), 256>>>(wembed, questions, Wo_w, Wo_b, p_gl, DD, DD, 768, 512, 2);
    leaf_combine_k<<<BSZ * SLEN, 256>>>();

    // shift-reduce scan: 63 sequential steps
    for (int t = 0; t < SLEN; t++) {
        step_gates_k<<<dim3(8, 20), 256>>>(t, ops, Ui_w, Uo_w, Uu_w, Uf_w);
        step_update_k<<<BSZ, 256>>>(t, ops, Ui_b, Uo_b, Uu_b, Uf_b);
    }
    r_gather_k<<<BSZ, 256>>>();

    // wq = r @ WQ_w^T + WQ_b   [512, 256]
    gemm_k<<<dim3(4, 4), 256>>>(p_r, nullptr, WQ_w, WQ_b, p_wq, DD, DD, DD, 0, 0);
    attention_k<<<BSZ, 256>>>(WP_w, WP_b);

    // head: out = tanh(att @ FC1^T + b1) @ FC2^T + b2
    gemm_k<<<dim3(4, 4), 256>>>(p_att, nullptr, FC1_w, FC1_b, p_hid, DD, DD, DD, 0, 1);
    gemm_k<<<dim3(4, 47), 256>>>(p_hid, nullptr, FC2_w, FC2_b, out, NOUTD, DD, NOUTD, 0, 0);

    (void)in_sizes; (void)out_size;
}

// round 8
// speedup vs baseline: 1.1899x; 1.1899x over previous
#include <cuda_runtime.h>
#include <cuda_bf16.h>
#include <math.h>
#include <stdint.h>

#define BSZ   512
#define SLEN  63
#define DD    256
#define VDIM  512
#define RR    196
#define NOUTD 3000
#define STK   (SLEN + 2)

// ---------------- scratch (static device arrays; no allocation) -------------
__device__ float g_vv   [(size_t)BSZ * RR * DD];
__device__ float g_wvi  [(size_t)BSZ * RR * DD];
__device__ float g_gl   [(size_t)BSZ * SLEN * 768];
__device__ float g_buffh[(size_t)BSZ * SLEN * DD];
__device__ float g_buffc[(size_t)BSZ * SLEN * DD];
__device__ float g_stackh[(size_t)BSZ * STK * DD];
__device__ float g_stackc[(size_t)BSZ * STK * DD];
__device__ float g_gates[(size_t)BSZ * 1280];
__device__ float g_r    [BSZ * DD];
__device__ float g_wq   [BSZ * DD];
__device__ float g_att  [BSZ * DD];
__device__ float g_hid  [BSZ * DD];
__device__ int   g_ptr  [BSZ];

// bf16 split buffers
__device__ __nv_bfloat16 g_v2  [(size_t)BSZ * RR * (2 * VDIM)];
__device__ __nv_bfloat16 g_vv2 [(size_t)BSZ * RR * (2 * DD)];
__device__ __nv_bfloat16 g_q2  [(size_t)BSZ * SLEN * (2 * DD)];
__device__ __nv_bfloat16 g_w3vv[256 * 3 * VDIM];
__device__ __nv_bfloat16 g_w3wv[256 * 3 * DD];
__device__ __nv_bfloat16 g_w3i [256 * 3 * DD];
__device__ __nv_bfloat16 g_w3u [256 * 3 * DD];
__device__ __nv_bfloat16 g_w3o [256 * 3 * DD];

// ---------------- packed f32x2 helpers ---------------------------------------
__device__ __forceinline__ unsigned long long pk2(float lo, float hi) {
    unsigned long long r;
    asm("mov.b64 %0, {%1, %2};" : "=l"(r) : "f"(lo), "f"(hi));
    return r;
}
__device__ __forceinline__ void upk2(unsigned long long v, float& lo, float& hi) {
    asm("mov.b64 {%0, %1}, %2;" : "=f"(lo), "=f"(hi) : "l"(v));
}
__device__ __forceinline__ unsigned long long ff2(unsigned long long a,
                                                  unsigned long long b,
                                                  unsigned long long c) {
    unsigned long long d;
    asm("fma.rn.f32x2 %0, %1, %2, %3;" : "=l"(d) : "l"(a), "l"(b), "l"(c));
    return d;
}
__device__ __forceinline__ float sigm(float x) { return 1.0f / (1.0f + expf(-x)); }

__device__ __forceinline__ uint32_t smem_u32(const void* p) {
    uint32_t a;
    asm("{ .reg .u64 t; cvta.to.shared.u64 t, %1; cvt.u32.u64 %0, t; }"
        : "=r"(a) : "l"(p));
    return a;
}
__device__ __forceinline__ void ldmx4(uint32_t& r0, uint32_t& r1,
                                      uint32_t& r2, uint32_t& r3, uint32_t addr) {
    asm volatile("ldmatrix.sync.aligned.m8n8.x4.shared.b16 {%0,%1,%2,%3}, [%4];"
                 : "=r"(r0), "=r"(r1), "=r"(r2), "=r"(r3) : "r"(addr));
}
__device__ __forceinline__ void mma16816(float& d0, float& d1, float& d2, float& d3,
                                         uint32_t a0, uint32_t a1, uint32_t a2, uint32_t a3,
                                         uint32_t b0, uint32_t b1) {
    asm volatile("mma.sync.aligned.m16n8k16.row.col.f32.bf16.bf16.f32 "
                 "{%0,%1,%2,%3}, {%4,%5,%6,%7}, {%8,%9}, {%0,%1,%2,%3};"
                 : "+f"(d0), "+f"(d1), "+f"(d2), "+f"(d3)
                 : "r"(a0), "r"(a1), "r"(a2), "r"(a3), "r"(b0), "r"(b1));
}

// ---------------------------------------------------------------------------
// Tensor-core (HMMA) split-bf16 GEMM.
// Cf[bm+r, coloff + bn + n] = act( sum_k A[r,k]*W[n,k] + bias[bn+n] ), N=256.
// A2: [M, 2K] bf16 (hi|lo). W3: [256, 3K] bf16 (Whi|Whi|Wlo).
// Virtual K' = 3K: (Ahi,Whi), (Alo,Whi), (Ahi,Wlo).
// Block: 256 thr, tile 128(M) x 64(N); grid.y = 4 over N=256.
// Chl (optional): bf16 hi|lo of the activated output, row stride 512.
// ---------------------------------------------------------------------------
#define APAD 72
__global__ __launch_bounds__(256) void mma_gemm(
    const __nv_bfloat16* __restrict__ A2,
    const __nv_bfloat16* __restrict__ W3,
    const float* __restrict__ bias,
    float* __restrict__ Cf,
    __nv_bfloat16* __restrict__ Chl,
    int K, int ldc, int coloff, int act)
{
    __shared__ __nv_bfloat16 As[128 * APAD];
    __shared__ __nv_bfloat16 Bs[64 * APAD];

    const int tid = threadIdx.x;
    const int wid = tid >> 5, lane = tid & 31;
    const int warp_m = wid & 3, warp_n = wid >> 2;
    const long bm = (long)blockIdx.x * 128;
    const int  bn = blockIdx.y * 64;

    const int nc = K / 64;
    const int vchunks = 3 * nc;
    const long lda = 2L * K;
    const long ldw = 3L * K;

    // ldmatrix lane address patterns (element offsets into padded smem)
    const int a_row = (lane & 7) + ((lane & 8) ? 8 : 0);
    const int a_col = (lane & 16) ? 8 : 0;
    const int b_row = (lane & 7) + ((lane & 16) ? 8 : 0);
    const int b_col = (lane & 8) ? 8 : 0;
    const uint32_t as_base = smem_u32(As);
    const uint32_t bs_base = smem_u32(Bs);

    // per-thread global load coords: A 128x64 (4 uint4/thr), B 64x64 (2 uint4/thr)
    const int arow0 = tid >> 3 >> 0;         // for q: row = (tid+256q)/8
    const int aj = tid & 7;
    (void)arow0;

    float d[2][4][4];
#pragma unroll
    for (int mt = 0; mt < 2; mt++)
#pragma unroll
        for (int nt = 0; nt < 4; nt++)
#pragma unroll
            for (int e = 0; e < 4; e++) d[mt][nt][e] = 0.0f;

    uint4 pa[4], pb[2];
    // prefetch chunk 0
    {
        const long ca = 0, cw = 0;
#pragma unroll
        for (int q = 0; q < 4; q++) {
            const int u = tid + 256 * q;
            pa[q] = *(const uint4*)(A2 + (bm + (u >> 3)) * lda + ca + (u & 7) * 8);
        }
#pragma unroll
        for (int q = 0; q < 2; q++) {
            const int u = tid + 256 * q;
            pb[q] = *(const uint4*)(W3 + (long)(bn + (u >> 3)) * ldw + cw + (u & 7) * 8);
        }
    }

    for (int c = 0; c < vchunks; c++) {
        // store prefetched chunk to smem
#pragma unroll
        for (int q = 0; q < 4; q++) {
            const int u = tid + 256 * q;
            *(uint4*)(As + (u >> 3) * APAD + (u & 7) * 8) = pa[q];
        }
#pragma unroll
        for (int q = 0; q < 2; q++) {
            const int u = tid + 256 * q;
            *(uint4*)(Bs + (u >> 3) * APAD + (u & 7) * 8) = pb[q];
        }
        __syncthreads();

        // prefetch next chunk
        if (c + 1 < vchunks) {
            const int cn = c + 1;
            const long ca = (long)((cn < 2 * nc) ? cn : (cn - 2 * nc)) * 64;
            const long cw = (long)cn * 64;
#pragma unroll
            for (int q = 0; q < 4; q++) {
                const int u = tid + 256 * q;
                pa[q] = *(const uint4*)(A2 + (bm + (u >> 3)) * lda + ca + (u & 7) * 8);
            }
#pragma unroll
            for (int q = 0; q < 2; q++) {
                const int u = tid + 256 * q;
                pb[q] = *(const uint4*)(W3 + (long)(bn + (u >> 3)) * ldw + cw + (u & 7) * 8);
            }
        }

        // MMA over 4 k16 slices
#pragma unroll
        for (int kk = 0; kk < 4; kk++) {
            uint32_t b0, b1, b2, b3;                       // n-tiles 0,1
            uint32_t b4, b5, b6, b7;                       // n-tiles 2,3
            {
                const int r = warp_n * 32 + b_row;
                const int cc = kk * 16 + b_col;
                ldmx4(b0, b1, b2, b3, bs_base + (r * APAD + cc) * 2);
                ldmx4(b4, b5, b6, b7, bs_base + ((r + 16) * APAD + cc) * 2);
            }
#pragma unroll
            for (int mt = 0; mt < 2; mt++) {
                uint32_t a0, a1, a2, a3;
                const int r = warp_m * 32 + mt * 16 + a_row;
                const int cc = kk * 16 + a_col;
                ldmx4(a0, a1, a2, a3, as_base + (r * APAD + cc) * 2);
                mma16816(d[mt][0][0], d[mt][0][1], d[mt][0][2], d[mt][0][3],
                         a0, a1, a2, a3, b0, b1);
                mma16816(d[mt][1][0], d[mt][1][1], d[mt][1][2], d[mt][1][3],
                         a0, a1, a2, a3, b2, b3);
                mma16816(d[mt][2][0], d[mt][2][1], d[mt][2][2], d[mt][2][3],
                         a0, a1, a2, a3, b4, b5);
                mma16816(d[mt][3][0], d[mt][3][1], d[mt][3][2], d[mt][3][3],
                         a0, a1, a2, a3, b6, b7);
            }
        }
        __syncthreads();
    }

    // epilogue: fragment (lane l: rows l/4, l/4+8; cols (l%4)*2, +1)
    const int qrow = lane >> 2;
    const int qcol = (lane & 3) * 2;
#pragma unroll
    for (int mt = 0; mt < 2; mt++) {
#pragma unroll
        for (int nt = 0; nt < 4; nt++) {
            const int colg = bn + warp_n * 32 + nt * 8 + qcol;
            const float bv0 = bias ? bias[colg]     : 0.0f;
            const float bv1 = bias ? bias[colg + 1] : 0.0f;
#pragma unroll
            for (int h = 0; h < 2; h++) {
                const long grow = bm + warp_m * 32 + mt * 16 + qrow + h * 8;
                float x0 = d[mt][nt][2 * h + 0] + bv0;
                float x1 = d[mt][nt][2 * h + 1] + bv1;
                if (act == 1)      { x0 = tanhf(x0); x1 = tanhf(x1); }
                else if (act == 2) { x0 = sigm(x0);  x1 = sigm(x1);  }
                *(float2*)(Cf + grow * ldc + coloff + colg) = make_float2(x0, x1);
                if (Chl) {
                    const __nv_bfloat16 h0 = __float2bfloat16(x0);
                    const __nv_bfloat16 h1 = __float2bfloat16(x1);
                    *(__nv_bfloat162*)(Chl + grow * 512 + colg) = __nv_bfloat162(h0, h1);
                    *(__nv_bfloat162*)(Chl + grow * 512 + 256 + colg) = __nv_bfloat162(
                        __float2bfloat16(x0 - __bfloat162float(h0)),
                        __float2bfloat16(x1 - __bfloat162float(h1)));
                }
            }
        }
    }
}

// ---------------- conversions: fp32 -> bf16 hi|lo -----------------------------
__global__ void split2_k(const float* __restrict__ A, const int* __restrict__ gidx,
                         __nv_bfloat16* __restrict__ O, int K)
{
    const long r = blockIdx.x;
    const long src = gidx ? (long)gidx[r] : r;
    const float* a = A + src * K;
    __nv_bfloat16* o = O + r * (2L * K);
    const int c = threadIdx.x * 4;
    if (c < K) {
        const float4 x = *(const float4*)(a + c);
        const __nv_bfloat16 h0 = __float2bfloat16(x.x), h1 = __float2bfloat16(x.y);
        const __nv_bfloat16 h2 = __float2bfloat16(x.z), h3 = __float2bfloat16(x.w);
        *(__nv_bfloat162*)(o + c)     = __nv_bfloat162(h0, h1);
        *(__nv_bfloat162*)(o + c + 2) = __nv_bfloat162(h2, h3);
        *(__nv_bfloat162*)(o + K + c) = __nv_bfloat162(
            __float2bfloat16(x.x - __bfloat162float(h0)),
            __float2bfloat16(x.y - __bfloat162float(h1)));
        *(__nv_bfloat162*)(o + K + c + 2) = __nv_bfloat162(
            __float2bfloat16(x.z - __bfloat162float(h2)),
            __float2bfloat16(x.w - __bfloat162float(h3)));
    }
}

__global__ void splitw3_k(const float* __restrict__ W, __nv_bfloat16* __restrict__ O, int K)
{
    const long r = blockIdx.x;
    const float* a = W + r * K;
    __nv_bfloat16* o = O + r * (3L * K);
    for (int c = threadIdx.x; c < K; c += blockDim.x) {
        const float x = a[c];
        const __nv_bfloat16 h = __float2bfloat16(x);
        o[c] = h;
        o[K + c] = h;
        o[2 * K + c] = __float2bfloat16(x - __bfloat162float(h));
    }
}

// ---------------- fp32 packed GEMM (small matmuls) -----------------------------
__global__ __launch_bounds__(256) void gemm_k(
    const float* __restrict__ A, const int* __restrict__ rowidx,
    const float* __restrict__ W, const float* __restrict__ bias,
    float* __restrict__ C, int N, int K, int ldc, int coloff, int act)
{
    __shared__ float As[16][132];
    __shared__ float Ws[16][68];
    const int tid = threadIdx.x;
    const int tx = tid & 15, ty = tid >> 4;
    const int lr = tid >> 2, lc = tid & 3;
    const long bm = (long)blockIdx.x * 128;
    const int  bn = blockIdx.y * 64;

    long ar0 = bm + lr, ar1 = bm + lr + 64;
    if (rowidx) { ar0 = rowidx[ar0]; ar1 = rowidx[ar1]; }
    const float* Ap0 = A + ar0 * (long)K;
    const float* Ap1 = A + ar1 * (long)K;
    const int wr = bn + lr;
    const bool wok = (wr < N);
    const float* Wp = W + (long)wr * K;

    unsigned long long acc[4][4];
#pragma unroll
    for (int p = 0; p < 4; p++)
#pragma unroll
        for (int c = 0; c < 4; c++) acc[p][c] = 0ULL;

    for (int k0 = 0; k0 < K; k0 += 16) {
        float4 a0 = *(const float4*)(Ap0 + k0 + lc * 4);
        float4 a1 = *(const float4*)(Ap1 + k0 + lc * 4);
        float4 w0 = wok ? *(const float4*)(Wp + k0 + lc * 4)
                        : make_float4(0.f, 0.f, 0.f, 0.f);
        __syncthreads();
        As[lc*4+0][lr] = a0.x; As[lc*4+1][lr] = a0.y;
        As[lc*4+2][lr] = a0.z; As[lc*4+3][lr] = a0.w;
        As[lc*4+0][lr+64] = a1.x; As[lc*4+1][lr+64] = a1.y;
        As[lc*4+2][lr+64] = a1.z; As[lc*4+3][lr+64] = a1.w;
        Ws[lc*4+0][lr] = w0.x; Ws[lc*4+1][lr] = w0.y;
        Ws[lc*4+2][lr] = w0.z; Ws[lc*4+3][lr] = w0.w;
        __syncthreads();
#pragma unroll
        for (int k = 0; k < 16; k++) {
            const float4 aA = *(const float4*)&As[k][ty*8];
            const float4 aB = *(const float4*)&As[k][ty*8+4];
            const float4 bb = *(const float4*)&Ws[k][tx*4];
            unsigned long long ap[4] = { pk2(aA.x,aA.y), pk2(aA.z,aA.w),
                                         pk2(aB.x,aB.y), pk2(aB.z,aB.w) };
            unsigned long long bd[4] = { pk2(bb.x,bb.x), pk2(bb.y,bb.y),
                                         pk2(bb.z,bb.z), pk2(bb.w,bb.w) };
#pragma unroll
            for (int p = 0; p < 4; p++)
#pragma unroll
                for (int c = 0; c < 4; c++)
                    acc[p][c] = ff2(ap[p], bd[c], acc[p][c]);
        }
    }

#pragma unroll
    for (int p = 0; p < 4; p++) {
        const long r0 = bm + ty*8 + p*2;
#pragma unroll
        for (int c = 0; c < 4; c++) {
            const int col = bn + tx*4 + c;
            if (col < N) {
                float lo, hi; upk2(acc[p][c], lo, hi);
                const float bv = bias ? bias[col] : 0.0f;
                lo += bv; hi += bv;
                if (act == 1)      { lo = tanhf(lo); hi = tanhf(hi); }
                else if (act == 2) { lo = sigm(lo);  hi = sigm(hi);  }
                C[r0 * (long)ldc + coloff + col] = lo;
                C[(r0+1) * (long)ldc + coloff + col] = hi;
            }
        }
    }
}

// ---------------- leaf combine --------------------------------------------------
__global__ void leaf_combine_k()
{
    const long i = (long)blockIdx.x * blockDim.x + threadIdx.x;
    const long row = i >> 8;
    const int  d = (int)(i & 255);
    const float gi = g_gl[row*768 + d];
    const float gu = g_gl[row*768 + 256 + d];
    const float go = g_gl[row*768 + 512 + d];
    const float bc = gi * gu;
    g_buffc[i] = bc;
    g_buffh[i] = go * tanhf(bc);
}

__global__ void ptr_init_k()
{
    const int i = blockIdx.x * blockDim.x + threadIdx.x;
    if (i < BSZ) g_ptr[i] = 0;
}

// ---------------- scan: gate GEMM (early-exit on push-only tiles) ----------------
__global__ __launch_bounds__(256) void step_gates_k(
    int t, const int* __restrict__ ops,
    const float* __restrict__ Ui, const float* __restrict__ Uo,
    const float* __restrict__ Uu, const float* __restrict__ Uf)
{
    __shared__ float As[16][68];
    __shared__ float Ws[16][68];
    __shared__ int sh_r[64], sh_l[64];
    __shared__ int anyred;

    const int tid = threadIdx.x;
    const int b0 = blockIdx.x * 64;
    if (tid == 0) anyred = 0;
    __syncthreads();
    if (tid < 64) {
        const int b = b0 + tid;
        const int p = g_ptr[b];
        sh_r[tid] = max(p - 1, 0);
        sh_l[tid] = max(p - 2, 0);
        if (ops[b * SLEN + t] == 1) anyred = 1;
    }
    __syncthreads();
    if (!anyred) return;

    const int seg = blockIdx.y >> 2;
    const int colbase = (blockIdx.y & 3) * 64;
    const float* W = (seg == 0) ? Ui : (seg == 1) ? Uo : (seg == 2) ? Uu : Uf;

    const int tx = tid & 15, ty = tid >> 4;
    const int lr = tid >> 2, lc = tid & 3;

    const float* Wp = W + (long)(colbase + lr) * DD;
    const float* SHb = g_stackh + (long)(b0 + lr) * STK * DD;
    const float* Sr = SHb + sh_r[lr] * DD;
    const float* Sl = SHb + sh_l[lr] * DD;

    unsigned long long acc[2][4];
#pragma unroll
    for (int p = 0; p < 2; p++)
#pragma unroll
        for (int c = 0; c < 4; c++) acc[p][c] = 0ULL;

    for (int k0 = 0; k0 < DD; k0 += 16) {
        float4 av;
        if (seg < 3) {
            const float4 x = *(const float4*)(Sr + k0 + lc*4);
            const float4 y = *(const float4*)(Sl + k0 + lc*4);
            av = make_float4(x.x+y.x, x.y+y.y, x.z+y.z, x.w+y.w);
        } else if (seg == 3) {
            av = *(const float4*)(Sl + k0 + lc*4);
        } else {
            av = *(const float4*)(Sr + k0 + lc*4);
        }
        const float4 wv = *(const float4*)(Wp + k0 + lc*4);
        __syncthreads();
        As[lc*4+0][lr] = av.x; As[lc*4+1][lr] = av.y;
        As[lc*4+2][lr] = av.z; As[lc*4+3][lr] = av.w;
        Ws[lc*4+0][lr] = wv.x; Ws[lc*4+1][lr] = wv.y;
        Ws[lc*4+2][lr] = wv.z; Ws[lc*4+3][lr] = wv.w;
        __syncthreads();
#pragma unroll
        for (int k = 0; k < 16; k++) {
            const float4 aa = *(const float4*)&As[k][ty*4];
            const float4 bb = *(const float4*)&Ws[k][tx*4];
            unsigned long long ap[2] = { pk2(aa.x,aa.y), pk2(aa.z,aa.w) };
            unsigned long long bd[4] = { pk2(bb.x,bb.x), pk2(bb.y,bb.y),
                                         pk2(bb.z,bb.z), pk2(bb.w,bb.w) };
#pragma unroll
            for (int p = 0; p < 2; p++)
#pragma unroll
                for (int c = 0; c < 4; c++)
                    acc[p][c] = ff2(ap[p], bd[c], acc[p][c]);
        }
    }

#pragma unroll
    for (int p = 0; p < 2; p++) {
        const long row = b0 + ty*4 + p*2;
#pragma unroll
        for (int c = 0; c < 4; c++) {
            const int col = seg * 256 + colbase + tx*4 + c;
            float lo, hi; upk2(acc[p][c], lo, hi);
            g_gates[row * 1280 + col] = lo;
            g_gates[(row+1) * 1280 + col] = hi;
        }
    }
}

__global__ void step_update_k(
    int t, const int* __restrict__ ops,
    const float* __restrict__ Uib, const float* __restrict__ Uob,
    const float* __restrict__ Uub, const float* __restrict__ Ufb)
{
    const int b = blockIdx.x;
    const int d = threadIdx.x;
    const int op = ops[b * SLEN + t];
    const int p = g_ptr[b];
    const int rix = max(p - 1, 0);
    const int lix = max(p - 2, 0);
    const long base = (long)b * STK * DD;

    if (op == 1) {
        const float* G = g_gates + (long)b * 1280;
        const float ig = sigm(G[d] + Uib[d]);
        const float og = sigm(G[256 + d] + Uob[d]);
        const float ug = tanhf(G[512 + d] + Uub[d]);
        const float f1 = sigm(G[768 + d] + Ufb[d]);
        const float f2 = sigm(G[1024 + d] + Ufb[d]);
        const float c1 = g_stackc[base + (long)lix * DD + d];
        const float c2 = g_stackc[base + (long)rix * DD + d];
        const float cn = ig * ug + f1 * c1 + f2 * c2;
        g_stackc[base + (long)lix * DD + d] = cn;
        g_stackh[base + (long)lix * DD + d] = og * tanhf(cn);
    } else if (op == 0) {
        const long bi = ((long)b * SLEN + t) * DD + d;
        g_stackh[base + (long)p * DD + d] = g_buffh[bi];
        g_stackc[base + (long)p * DD + d] = g_buffc[bi];
    }
    __syncthreads();
    if (d == 0)
        g_ptr[b] = p + (op == 0 ? 1 : (op == 1 ? -1 : 0));
}

__global__ void r_gather_k()
{
    const int b = blockIdx.x, d = threadIdx.x;
    const int ix = max(g_ptr[b] - 1, 0);
    g_r[b * DD + d] = g_stackh[((long)b * STK + ix) * DD + d];
}

__global__ void attention_k(const float* __restrict__ WPw,
                            const float* __restrict__ WPb)
{
    const int b = blockIdx.x, tid = threadIdx.x;
    const int warp = tid >> 5, lane = tid & 31;
    __shared__ float s_wq[256], s_wp[256], s_sc[RR], red[16];

    s_wq[tid] = g_wq[b * DD + tid];
    s_wp[tid] = WPw[tid];
    __syncthreads();

    const float wpb = WPb[0];
    for (int r = warp; r < RR; r += 8) {
        const float* vrow = g_wvi + ((long)b * RR + r) * DD;
        float acc = 0.f;
        for (int d = lane; d < DD; d += 32)
            acc += tanhf(s_wq[d] + vrow[d]) * s_wp[d];
#pragma unroll
        for (int o = 16; o; o >>= 1) acc += __shfl_xor_sync(~0u, acc, o);
        if (lane == 0) s_sc[r] = acc + wpb;
    }
    __syncthreads();

    float v = (tid < RR) ? s_sc[tid] : -1e30f;
    float m = v;
#pragma unroll
    for (int o = 16; o; o >>= 1) m = fmaxf(m, __shfl_xor_sync(~0u, m, o));
    if (lane == 0) red[warp] = m;
    __syncthreads();
    if (tid == 0) {
        float mm = red[0];
        for (int q = 1; q < 8; q++) mm = fmaxf(mm, red[q]);
        red[0] = mm;
    }
    __syncthreads();
    const float mm = red[0];
    float e = (tid < RR) ? expf(v - mm) : 0.f;
    float s = e;
#pragma unroll
    for (int o = 16; o; o >>= 1) s += __shfl_xor_sync(~0u, s, o);
    if (lane == 0) red[8 + warp] = s;
    __syncthreads();
    if (tid == 0) {
        float ss = 0.f;
        for (int q = 0; q < 8; q++) ss += red[8 + q];
        red[8] = ss;
    }
    __syncthreads();
    const float inv = 1.0f / red[8];
    if (tid < RR) s_sc[tid] = e * inv;
    __syncthreads();

    float acc = g_r[b * DD + tid];
    const float* vb = g_vv + (long)b * RR * DD;
    for (int r = 0; r < RR; r++)
        acc += s_sc[r] * vb[r * DD + tid];
    g_att[b * DD + tid] = acc;
}

// ---------------------------------------------------------------------------
template <typename T>
static void* symaddr_raw(T& sym) {
    void* p = nullptr;
    cudaGetSymbolAddress(&p, sym);
    return p;
}

extern "C" void kernel_launch(void* const* d_in, const int* in_sizes, int n_in,
                              void* d_out, int out_size)
{
    const float* v         = (const float*)d_in[0];
    const int*   questions = (const int*)d_in[1];
    const int*   ops       = (const int*)d_in[2];
    int i = (n_in >= 30) ? 4 : 3;
    const float* wembed = (const float*)d_in[i++];
    const float* W_w  = (const float*)d_in[i++]; const float* W_b  = (const float*)d_in[i++];
    const float* Wi_w = (const float*)d_in[i++]; const float* Wi_b = (const float*)d_in[i++];
    const float* Wu_w = (const float*)d_in[i++]; const float* Wu_b = (const float*)d_in[i++];
    const float* Wo_w = (const float*)d_in[i++]; const float* Wo_b = (const float*)d_in[i++];
    const float* Ui_w = (const float*)d_in[i++]; const float* Ui_b = (const float*)d_in[i++];
    const float* Uf_w = (const float*)d_in[i++]; const float* Uf_b = (const float*)d_in[i++];
    const float* Uo_w = (const float*)d_in[i++]; const float* Uo_b = (const float*)d_in[i++];
    const float* Uu_w = (const float*)d_in[i++]; const float* Uu_b = (const float*)d_in[i++];
    const float* WQ_w = (const float*)d_in[i++]; const float* WQ_b = (const float*)d_in[i++];
    const float* WV_w = (const float*)d_in[i++];
    const float* WP_w = (const float*)d_in[i++]; const float* WP_b = (const float*)d_in[i++];
    const float* FC1_w = (const float*)d_in[i++]; const float* FC1_b = (const float*)d_in[i++];
    const float* FC2_w = (const float*)d_in[i++]; const float* FC2_b = (const float*)d_in[i++];
    float* out = (float*)d_out;

    float* p_vv  = (float*)symaddr_raw(g_vv);
    float* p_gl  = (float*)symaddr_raw(g_gl);
    float* p_wvi = (float*)symaddr_raw(g_wvi);
    float* p_r   = (float*)symaddr_raw(g_r);
    float* p_wq  = (float*)symaddr_raw(g_wq);
    float* p_att = (float*)symaddr_raw(g_att);
    float* p_hid = (float*)symaddr_raw(g_hid);
    __nv_bfloat16* p_v2   = (__nv_bfloat16*)symaddr_raw(g_v2);
    __nv_bfloat16* p_vv2  = (__nv_bfloat16*)symaddr_raw(g_vv2);
    __nv_bfloat16* p_q2   = (__nv_bfloat16*)symaddr_raw(g_q2);
    __nv_bfloat16* p_w3vv = (__nv_bfloat16*)symaddr_raw(g_w3vv);
    __nv_bfloat16* p_w3wv = (__nv_bfloat16*)symaddr_raw(g_w3wv);
    __nv_bfloat16* p_w3i  = (__nv_bfloat16*)symaddr_raw(g_w3i);
    __nv_bfloat16* p_w3u  = (__nv_bfloat16*)symaddr_raw(g_w3u);
    __nv_bfloat16* p_w3o  = (__nv_bfloat16*)symaddr_raw(g_w3o);

    ptr_init_k<<<2, 256>>>();

    // conversions to bf16 hi|lo
    split2_k<<<BSZ * RR, 128>>>(v, nullptr, p_v2, VDIM);
    split2_k<<<BSZ * SLEN, 128>>>(wembed, questions, p_q2, DD);
    splitw3_k<<<256, 128>>>(W_w,  p_w3vv, VDIM);
    splitw3_k<<<256, 128>>>(WV_w, p_w3wv, DD);
    splitw3_k<<<256, 128>>>(Wi_w, p_w3i,  DD);
    splitw3_k<<<256, 128>>>(Wu_w, p_w3u,  DD);
    splitw3_k<<<256, 128>>>(Wo_w, p_w3o,  DD);

    // big GEMMs on tensor cores (classic HMMA path)
    mma_gemm<<<dim3(784, 4), 256>>>(p_v2, p_w3vv, W_b, p_vv, p_vv2, VDIM, DD, 0, 1);
    mma_gemm<<<dim3(252, 4), 256>>>(p_q2, p_w3i, Wi_b, p_gl, nullptr, DD, 768, 0,   2);
    mma_gemm<<<dim3(252, 4), 256>>>(p_q2, p_w3u, Wu_b, p_gl, nullptr, DD, 768, 256, 1);
    mma_gemm<<<dim3(252, 4), 256>>>(p_q2, p_w3o, Wo_b, p_gl, nullptr, DD, 768, 512, 2);
    leaf_combine_k<<<BSZ * SLEN, 256>>>();
    mma_gemm<<<dim3(784, 4), 256>>>(p_vv2, p_w3wv, nullptr, p_wvi, nullptr, DD, DD, 0, 0);

    // shift-reduce scan
    for (int t = 0; t < SLEN; t++) {
        step_gates_k<<<dim3(8, 20), 256>>>(t, ops, Ui_w, Uo_w, Uu_w, Uf_w);
        step_update_k<<<BSZ, 256>>>(t, ops, Ui_b, Uo_b, Uu_b, Uf_b);
    }
    r_gather_k<<<BSZ, 256>>>();

    gemm_k<<<dim3(4, 4), 256>>>(p_r, nullptr, WQ_w, WQ_b, p_wq, DD, DD, DD, 0, 0);
    attention_k<<<BSZ, 256>>>(WP_w, WP_b);
    gemm_k<<<dim3(4, 4), 256>>>(p_att, nullptr, FC1_w, FC1_b, p_hid, DD, DD, DD, 0, 1);
    gemm_k<<<dim3(4, 47), 256>>>(p_hid, nullptr, FC2_w, FC2_b, out, NOUTD, DD, NOUTD, 0, 0);

    (void)in_sizes; (void)out_size;
}